// round 1
// baseline (speedup 1.0000x reference)
#include <cuda_runtime.h>
#include <cuda_bf16.h>

// rnn_two: out = h2_last @ Wo for two stacked LINEAR SimpleRNNs.
// Linearity => out = sum_t x_t @ A_t with A_t = W1 @ S(15-t) @ Wo,
// S(m) = sum_{j=0..m} U1^j W2 U2^(m-j), built by log-depth doubling:
//   S(m) = S(k-1) @ U2^(m-k+1) + U1^k @ S(m-k).
// Then one big GEMM: out[8192,256] = Xflat[8192,4096] @ Acat[4096,256].

#define NN 256
#define TT 16
#define MSZ (NN * NN)
#define BB 8192
#define KTOT (TT * NN)   // 4096

// Scratch (device globals: no allocation allowed)
__device__ __align__(16) float g_P1[9][MSZ];    // U1^1..U1^8 (index = power)
__device__ __align__(16) float g_P2[9][MSZ];    // U2^1..U2^8
__device__ __align__(16) float g_S[TT][MSZ];    // S(0)..S(15)
__device__ __align__(16) float g_TMP[TT][MSZ];  // W1 @ S(m)
__device__ __align__(16) float g_A[TT * MSZ];   // Acat[(t*256+k)*256 + n]

// ---------------------------------------------------------------------------
// 64x64-tile fp32 matmul core for 256x256 operands (K=256), accumulating into
// registers. Block = 256 threads, each thread owns a 4x4 output patch.
// As stored k-major [16][64] so both operand reads are float4 from smem.
// ---------------------------------------------------------------------------
__device__ __forceinline__ void mm_accum_256(
    float acc[4][4],
    const float* __restrict__ A, const float* __restrict__ B,
    int rowBase, int colBase,
    float As[16][64], float Bs[16][64])
{
    const int tid = threadIdx.x;
    const int ty = tid >> 4, tx = tid & 15;
    const int ar = tid & 63, akq = tid >> 6;   // A: row, k-quad
    const int bkr = tid >> 4, bcq = tid & 15;  // B: k-row, col-quad

    for (int kb = 0; kb < NN / 16; ++kb) {
        float4 av = *(const float4*)&A[(rowBase + ar) * NN + kb * 16 + akq * 4];
        As[akq * 4 + 0][ar] = av.x;
        As[akq * 4 + 1][ar] = av.y;
        As[akq * 4 + 2][ar] = av.z;
        As[akq * 4 + 3][ar] = av.w;
        *(float4*)&Bs[bkr][bcq * 4] =
            *(const float4*)&B[(kb * 16 + bkr) * NN + colBase + bcq * 4];
        __syncthreads();
#pragma unroll
        for (int kk = 0; kk < 16; ++kk) {
            float4 a = *(const float4*)&As[kk][ty * 4];
            float4 b = *(const float4*)&Bs[kk][tx * 4];
            float a4[4] = {a.x, a.y, a.z, a.w};
            float b4[4] = {b.x, b.y, b.z, b.w};
#pragma unroll
            for (int i = 0; i < 4; ++i)
#pragma unroll
                for (int j = 0; j < 4; ++j)
                    acc[i][j] = fmaf(a4[i], b4[j], acc[i][j]);
        }
        __syncthreads();
    }
}

__device__ __forceinline__ void store_tile(
    const float acc[4][4], float* __restrict__ C, int ldc,
    int rowBase, int colBase)
{
    const int tid = threadIdx.x;
    const int ty = tid >> 4, tx = tid & 15;
#pragma unroll
    for (int i = 0; i < 4; ++i) {
        float4 v = make_float4(acc[i][0], acc[i][1], acc[i][2], acc[i][3]);
        *(float4*)&C[(rowBase + ty * 4 + i) * ldc + colBase + tx * 4] = v;
    }
}

// ---------------------------------------------------------------------------
// Precompute kernels
// ---------------------------------------------------------------------------
__global__ void k_init(const float* __restrict__ U1,
                       const float* __restrict__ U2,
                       const float* __restrict__ W2)
{
    int i = blockIdx.x * blockDim.x + threadIdx.x;  // 65536 total
    g_P1[1][i] = U1[i];
    g_P2[1][i] = U2[i];
    g_S[0][i]  = W2[i];
}

// Stage with max known power/index M. Jobs:
//   [0, e_pow)        : P1[M+1+j] = P1[M] @ P1[1+j]
//   [e_pow, 2e_pow)   : P2 same
//   [2e_pow, +e_s)    : m = M+j : S[m] = S[M-1] @ P2[m-M+1] + P1[M] @ S[m-M]
__global__ void k_stage(int M)
{
    const int e_pow = min(M, 8 - M);
    const int job = blockIdx.y;
    const int tile = blockIdx.x;
    const int rowBase = (tile >> 2) * 64;
    const int colBase = (tile & 3) * 64;

    __shared__ float As[16][64];
    __shared__ float Bs[16][64];
    float acc[4][4] = {};

    const float *A0, *B0, *A1 = nullptr, *B1 = nullptr;
    float* C;
    if (job < e_pow) {
        int j = job + 1;
        A0 = g_P1[M]; B0 = g_P1[j]; C = g_P1[M + j];
    } else if (job < 2 * e_pow) {
        int j = job - e_pow + 1;
        A0 = g_P2[M]; B0 = g_P2[j]; C = g_P2[M + j];
    } else {
        int m = M + (job - 2 * e_pow);
        A0 = g_S[M - 1]; B0 = g_P2[m - M + 1];
        A1 = g_P1[M];    B1 = g_S[m - M];
        C = g_S[m];
    }

    mm_accum_256(acc, A0, B0, rowBase, colBase, As, Bs);
    if (A1) mm_accum_256(acc, A1, B1, rowBase, colBase, As, Bs);
    store_tile(acc, C, NN, rowBase, colBase);
}

__global__ void k_tmp(const float* __restrict__ W1)
{
    const int m = blockIdx.y;
    const int tile = blockIdx.x;
    const int rowBase = (tile >> 2) * 64, colBase = (tile & 3) * 64;
    __shared__ float As[16][64];
    __shared__ float Bs[16][64];
    float acc[4][4] = {};
    mm_accum_256(acc, W1, g_S[m], rowBase, colBase, As, Bs);
    store_tile(acc, g_TMP[m], NN, rowBase, colBase);
}

__global__ void k_afinal(const float* __restrict__ Wo)
{
    const int t = blockIdx.y;  // time index of A_t
    const int tile = blockIdx.x;
    const int rowBase = (tile >> 2) * 64, colBase = (tile & 3) * 64;
    __shared__ float As[16][64];
    __shared__ float Bs[16][64];
    float acc[4][4] = {};
    mm_accum_256(acc, g_TMP[15 - t], Wo, rowBase, colBase, As, Bs);
    store_tile(acc, g_A + t * MSZ, NN, rowBase, colBase);
}

// ---------------------------------------------------------------------------
// Main GEMM: out[8192,256] = X[8192,4096] @ g_A[4096,256]
// BM=BN=64, BK=16, 256 threads, 4x4 per thread. Grid (128, 4).
// ---------------------------------------------------------------------------
__global__ void k_gemm(const float* __restrict__ X, float* __restrict__ out)
{
    __shared__ float As[16][64];
    __shared__ float Bs[16][64];
    const int tid = threadIdx.x;
    const int ty = tid >> 4, tx = tid & 15;
    const int rowBase = blockIdx.x * 64;
    const int colBase = blockIdx.y * 64;
    const int ar = tid & 63, akq = tid >> 6;
    const int bkr = tid >> 4, bcq = tid & 15;

    float acc[4][4] = {};

    for (int kb = 0; kb < KTOT / 16; ++kb) {
        float4 av = *(const float4*)&X[(rowBase + ar) * KTOT + kb * 16 + akq * 4];
        As[akq * 4 + 0][ar] = av.x;
        As[akq * 4 + 1][ar] = av.y;
        As[akq * 4 + 2][ar] = av.z;
        As[akq * 4 + 3][ar] = av.w;
        *(float4*)&Bs[bkr][bcq * 4] =
            *(const float4*)&g_A[(kb * 16 + bkr) * NN + colBase + bcq * 4];
        __syncthreads();
#pragma unroll
        for (int kk = 0; kk < 16; ++kk) {
            float4 a = *(const float4*)&As[kk][ty * 4];
            float4 b = *(const float4*)&Bs[kk][tx * 4];
            float a4[4] = {a.x, a.y, a.z, a.w};
            float b4[4] = {b.x, b.y, b.z, b.w};
#pragma unroll
            for (int i = 0; i < 4; ++i)
#pragma unroll
                for (int j = 0; j < 4; ++j)
                    acc[i][j] = fmaf(a4[i], b4[j], acc[i][j]);
        }
        __syncthreads();
    }

#pragma unroll
    for (int i = 0; i < 4; ++i) {
        float4 v = make_float4(acc[i][0], acc[i][1], acc[i][2], acc[i][3]);
        *(float4*)&out[(rowBase + ty * 4 + i) * NN + colBase + tx * 4] = v;
    }
}

// ---------------------------------------------------------------------------
extern "C" void kernel_launch(void* const* d_in, const int* in_sizes, int n_in,
                              void* d_out, int out_size)
{
    const float* x  = (const float*)d_in[0];  // [8192,16,256]
    const float* W1 = (const float*)d_in[1];
    const float* U1 = (const float*)d_in[2];
    const float* W2 = (const float*)d_in[3];
    const float* U2 = (const float*)d_in[4];
    const float* Wo = (const float*)d_in[5];
    float* out = (float*)d_out;               // [8192,256]

    k_init<<<MSZ / 256, 256>>>(U1, U2, W2);
    k_stage<<<dim3(16, 3),  256>>>(1);   // P2;            S(1)
    k_stage<<<dim3(16, 6),  256>>>(2);   // P3,P4;         S(2),S(3)
    k_stage<<<dim3(16, 12), 256>>>(4);   // P5..P8;        S(4..7)
    k_stage<<<dim3(16, 8),  256>>>(8);   //                S(8..15)
    k_tmp<<<dim3(16, 16), 256>>>(W1);    // TMP[m] = W1 @ S(m)
    k_afinal<<<dim3(16, 16), 256>>>(Wo); // Acat[t] = TMP[15-t] @ Wo
    k_gemm<<<dim3(BB / 64, NN / 64), 256>>>(x, out);
}

// round 3
// speedup vs baseline: 2.2016x; 2.2016x over previous
#include <cuda_runtime.h>
#include <cuda_bf16.h>
#include <cstdint>

// rnn_two: out = h2_last @ Wo for two stacked LINEAR SimpleRNNs.
// Linearity => out = sum_t x_t @ A_t with A_t = W1 @ S(15-t) @ Wo,
// S(m) = sum_{j=0..m} U1^j W2 U2^(m-j), via log-depth doubling.
// Main GEMM out[8192,256] = X[8192,4096] @ Acat[4096,256] runs on warp-level
// mma.sync (bf16 hi/lo split, 3 products, fp32 accum) — tcgen05 is not
// available on this sm_100 (non-'a') build target.

#define NN 256
#define TT 16
#define MSZ (NN * NN)
#define BB 8192
#define KTOT (TT * NN)   // 4096

// Scratch (device globals: no allocation allowed)
__device__ __align__(16) float g_P1[9][MSZ];
__device__ __align__(16) float g_P2[9][MSZ];
__device__ __align__(16) float g_S[TT][MSZ];
__device__ __align__(16) float g_TMP[TT][MSZ];
// Acat transposed + bf16-split: g_Bhi/lo[n][kglobal], kglobal = t*256 + j
__device__ __align__(16) __nv_bfloat16 g_Bhi[NN * KTOT];
__device__ __align__(16) __nv_bfloat16 g_Blo[NN * KTOT];

// ---------------------------------------------------------------------------
// SIMT 64x64-tile fp32 matmul core for 256x256 operands (precompute only)
// ---------------------------------------------------------------------------
__device__ __forceinline__ void mm_accum_256(
    float acc[4][4],
    const float* __restrict__ A, const float* __restrict__ B,
    int rowBase, int colBase,
    float As[16][64], float Bs[16][64])
{
    const int tid = threadIdx.x;
    const int ty = tid >> 4, tx = tid & 15;
    const int ar = tid & 63, akq = tid >> 6;
    const int bkr = tid >> 4, bcq = tid & 15;

    for (int kb = 0; kb < NN / 16; ++kb) {
        float4 av = *(const float4*)&A[(rowBase + ar) * NN + kb * 16 + akq * 4];
        As[akq * 4 + 0][ar] = av.x;
        As[akq * 4 + 1][ar] = av.y;
        As[akq * 4 + 2][ar] = av.z;
        As[akq * 4 + 3][ar] = av.w;
        *(float4*)&Bs[bkr][bcq * 4] =
            *(const float4*)&B[(kb * 16 + bkr) * NN + colBase + bcq * 4];
        __syncthreads();
#pragma unroll
        for (int kk = 0; kk < 16; ++kk) {
            float4 a = *(const float4*)&As[kk][ty * 4];
            float4 b = *(const float4*)&Bs[kk][tx * 4];
            float a4[4] = {a.x, a.y, a.z, a.w};
            float b4[4] = {b.x, b.y, b.z, b.w};
#pragma unroll
            for (int i = 0; i < 4; ++i)
#pragma unroll
                for (int j = 0; j < 4; ++j)
                    acc[i][j] = fmaf(a4[i], b4[j], acc[i][j]);
        }
        __syncthreads();
    }
}

__device__ __forceinline__ void store_tile(
    const float acc[4][4], float* __restrict__ C, int ldc,
    int rowBase, int colBase)
{
    const int tid = threadIdx.x;
    const int ty = tid >> 4, tx = tid & 15;
#pragma unroll
    for (int i = 0; i < 4; ++i) {
        float4 v = make_float4(acc[i][0], acc[i][1], acc[i][2], acc[i][3]);
        *(float4*)&C[(rowBase + ty * 4 + i) * ldc + colBase + tx * 4] = v;
    }
}

// ---------------------------------------------------------------------------
// Precompute kernels
// ---------------------------------------------------------------------------
__global__ void k_init(const float* __restrict__ U1,
                       const float* __restrict__ U2,
                       const float* __restrict__ W2)
{
    int i = blockIdx.x * blockDim.x + threadIdx.x;
    g_P1[1][i] = U1[i];
    g_P2[1][i] = U2[i];
    g_S[0][i]  = W2[i];
}

__global__ void k_stage(int M)
{
    const int e_pow = min(M, 8 - M);
    const int job = blockIdx.y;
    const int tile = blockIdx.x;
    const int rowBase = (tile >> 2) * 64;
    const int colBase = (tile & 3) * 64;

    __shared__ float As[16][64];
    __shared__ float Bs[16][64];
    float acc[4][4] = {};

    const float *A0, *B0, *A1 = nullptr, *B1 = nullptr;
    float* C;
    if (job < e_pow) {
        int j = job + 1;
        A0 = g_P1[M]; B0 = g_P1[j]; C = g_P1[M + j];
    } else if (job < 2 * e_pow) {
        int j = job - e_pow + 1;
        A0 = g_P2[M]; B0 = g_P2[j]; C = g_P2[M + j];
    } else {
        int m = M + (job - 2 * e_pow);
        A0 = g_S[M - 1]; B0 = g_P2[m - M + 1];
        A1 = g_P1[M];    B1 = g_S[m - M];
        C = g_S[m];
    }

    mm_accum_256(acc, A0, B0, rowBase, colBase, As, Bs);
    if (A1) mm_accum_256(acc, A1, B1, rowBase, colBase, As, Bs);
    store_tile(acc, C, NN, rowBase, colBase);
}

__global__ void k_tmp(const float* __restrict__ W1)
{
    const int m = blockIdx.y;
    const int tile = blockIdx.x;
    const int rowBase = (tile >> 2) * 64, colBase = (tile & 3) * 64;
    __shared__ float As[16][64];
    __shared__ float Bs[16][64];
    float acc[4][4] = {};
    mm_accum_256(acc, W1, g_S[m], rowBase, colBase, As, Bs);
    store_tile(acc, g_TMP[m], NN, rowBase, colBase);
}

// A_t = TMP[15-t] @ Wo, stored transposed + bf16 hi/lo split.
__global__ void k_afinal(const float* __restrict__ Wo)
{
    const int t = blockIdx.y;
    const int tile = blockIdx.x;
    const int rowBase = (tile >> 2) * 64, colBase = (tile & 3) * 64;
    __shared__ float As[16][64];
    __shared__ float Bs[16][64];
    float acc[4][4] = {};
    mm_accum_256(acc, g_TMP[15 - t], Wo, rowBase, colBase, As, Bs);

    const int tid = threadIdx.x;
    const int ty = tid >> 4, tx = tid & 15;
    const int kbase = t * NN + rowBase + ty * 4;   // multiple of 4
#pragma unroll
    for (int j = 0; j < 4; ++j) {
        int n = colBase + tx * 4 + j;
        __nv_bfloat16 h[4], l[4];
#pragma unroll
        for (int i = 0; i < 4; ++i) {
            float v = acc[i][j];
            h[i] = __float2bfloat16_rn(v);
            l[i] = __float2bfloat16_rn(v - __bfloat162float(h[i]));
        }
        *(uint64_t*)&g_Bhi[(size_t)n * KTOT + kbase] = *(uint64_t*)h;
        *(uint64_t*)&g_Blo[(size_t)n * KTOT + kbase] = *(uint64_t*)l;
    }
}

// ---------------------------------------------------------------------------
// Main GEMM on mma.sync: out[8192,256] = X @ Acat.
// CTA 128x128, 8 warps (warp w: rows w*16..w*16+15, all 128 cols).
// B staged in SW128-swizzled smem via cp.async (double buffer, BK=64);
// A fragments loaded directly from gmem with 1-step register prefetch.
// ---------------------------------------------------------------------------
#define BM 128
#define BN 128
#define BKC 64                  // k per smem chunk
#define NCHUNK (KTOT / BKC)     // 64
#define BUFB 32768              // bhi 16K + blo 16K
#define GEMM_SMEM (2 * BUFB)    // 64 KB

__device__ __forceinline__ uint32_t s2u(const void* p) {
    uint32_t a;
    asm("{ .reg .u64 t; cvta.to.shared.u64 t, %1; cvt.u32.u64 %0, t; }"
        : "=r"(a) : "l"(p));
    return a;
}
__device__ __forceinline__ uint32_t sw128(uint32_t b) {
    return b ^ ((b >> 3) & 0x70);
}
__device__ __forceinline__ void cp16(uint32_t dst, const void* src) {
    asm volatile("cp.async.cg.shared.global [%0], [%1], 16;"
                 :: "r"(dst), "l"(src));
}
__device__ __forceinline__ void cp_commit() {
    asm volatile("cp.async.commit_group;");
}
__device__ __forceinline__ void cp_wait1() {
    asm volatile("cp.async.wait_group 1;" ::: "memory");
}
__device__ __forceinline__ void ldsm4(uint32_t r[4], uint32_t addr) {
    asm volatile("ldmatrix.sync.aligned.m8n8.x4.shared.b16 {%0,%1,%2,%3}, [%4];"
                 : "=r"(r[0]), "=r"(r[1]), "=r"(r[2]), "=r"(r[3]) : "r"(addr));
}
__device__ __forceinline__ void mma16816(float c[4], const uint32_t a[4],
                                         uint32_t b0, uint32_t b1) {
    asm volatile(
        "mma.sync.aligned.m16n8k16.row.col.f32.bf16.bf16.f32 "
        "{%0,%1,%2,%3}, {%4,%5,%6,%7}, {%8,%9}, {%0,%1,%2,%3};"
        : "+f"(c[0]), "+f"(c[1]), "+f"(c[2]), "+f"(c[3])
        : "r"(a[0]), "r"(a[1]), "r"(a[2]), "r"(a[3]), "r"(b0), "r"(b1));
}
__device__ __forceinline__ void splitf2(float2 v, uint32_t& hi, uint32_t& lo) {
    __nv_bfloat162 h = __float22bfloat162_rn(v);
    float2 hf = __bfloat1622float2(h);
    __nv_bfloat162 L = __float22bfloat162_rn(make_float2(v.x - hf.x, v.y - hf.y));
    hi = *reinterpret_cast<uint32_t*>(&h);
    lo = *reinterpret_cast<uint32_t*>(&L);
}

__global__ void __launch_bounds__(256)
k_gemm_mma(const float* __restrict__ X, float* __restrict__ out)
{
    extern __shared__ char smem[];
    const uint32_t sb = s2u(smem);
    const int tid = threadIdx.x;
    const int w = tid >> 5, l = tid & 31;
    const int rowBase = blockIdx.x * BM;
    const int colBase = blockIdx.y * BN;

    // ---- B chunk loader: chunk c -> buffer b (cp.async, swizzled) ----
    auto loadB = [&](int c, int b) {
        const uint32_t dhi = sb + b * BUFB;
        const uint32_t dlo = dhi + 16384;
#pragma unroll
        for (int p = 0; p < 4; ++p) {
            int id = tid + p * 256;           // 1024 chunks of 16B
            int n = id >> 3, cc = id & 7;
            uint32_t off = sw128((uint32_t)(n * 128 + cc * 16));
            size_t g = (size_t)(colBase + n) * KTOT + c * BKC + cc * 8;
            cp16(dhi + off, &g_Bhi[g]);
            cp16(dlo + off, &g_Blo[g]);
        }
    };

    loadB(0, 0);
    cp_commit();

    // A fragment pointers (row-major X, this thread's lanes)
    const float* p0 = X + (size_t)(rowBase + w * 16 + (l >> 2)) * KTOT + (l & 3) * 2;
    const float* p1 = p0 + (size_t)8 * KTOT;

    // prefetch k16 = 0
    float2 aN0 = *(const float2*)(p0);
    float2 aN1 = *(const float2*)(p1);
    float2 aN2 = *(const float2*)(p0 + 8);
    float2 aN3 = *(const float2*)(p1 + 8);

    float acc[16][4];
#pragma unroll
    for (int j = 0; j < 16; ++j)
#pragma unroll
        for (int q = 0; q < 4; ++q) acc[j][q] = 0.f;

    // per-thread ldmatrix address pieces
    const uint32_t tb0 = (uint32_t)((((l >> 4) * 8) + (l & 7)) * 128 + ((l >> 3) & 1) * 16);
    const uint32_t swx = (uint32_t)((l & 7) << 4);

    for (int c = 0; c < NCHUNK; ++c) {
        if (c + 1 < NCHUNK) loadB(c + 1, (c + 1) & 1);
        cp_commit();
        cp_wait1();
        __syncthreads();

        const uint32_t bhiB = sb + (c & 1) * BUFB;
        const uint32_t bloB = bhiB + 16384;

#pragma unroll
        for (int kk = 0; kk < 4; ++kk) {
            // convert current A fragments
            uint32_t ahi[4], alo[4];
            splitf2(aN0, ahi[0], alo[0]);
            splitf2(aN1, ahi[1], alo[1]);
            splitf2(aN2, ahi[2], alo[2]);
            splitf2(aN3, ahi[3], alo[3]);

            // prefetch next k16
            int kn = c * 4 + kk + 1;
            if (kn < KTOT / 16) {
                int kb = kn * 16;
                aN0 = *(const float2*)(p0 + kb);
                aN1 = *(const float2*)(p1 + kb);
                aN2 = *(const float2*)(p0 + kb + 8);
                aN3 = *(const float2*)(p1 + kb + 8);
            }

#pragma unroll
            for (int jp = 0; jp < 8; ++jp) {   // n8-tile pairs (2jp, 2jp+1)
                uint32_t aoff = ((tb0 + (uint32_t)(kk * 32) + (uint32_t)(jp * 2048)) ^ swx);
                uint32_t bh[4], bl[4];
                ldsm4(bh, bhiB + aoff);
                ldsm4(bl, bloB + aoff);
                mma16816(acc[2 * jp],     ahi, bh[0], bh[1]);
                mma16816(acc[2 * jp],     ahi, bl[0], bl[1]);
                mma16816(acc[2 * jp],     alo, bh[0], bh[1]);
                mma16816(acc[2 * jp + 1], ahi, bh[2], bh[3]);
                mma16816(acc[2 * jp + 1], ahi, bl[2], bl[3]);
                mma16816(acc[2 * jp + 1], alo, bh[2], bh[3]);
            }
        }
        __syncthreads();
    }

    // epilogue: D fragment c0,c1=(m, n,n+1), c2,c3=(m+8, n,n+1)
    const int r0 = rowBase + w * 16 + (l >> 2);
    const int nb = colBase + (l & 3) * 2;
#pragma unroll
    for (int j = 0; j < 16; ++j) {
        int n = nb + j * 8;
        *(float2*)&out[(size_t)r0 * NN + n] = make_float2(acc[j][0], acc[j][1]);
        *(float2*)&out[(size_t)(r0 + 8) * NN + n] = make_float2(acc[j][2], acc[j][3]);
    }
}

// ---------------------------------------------------------------------------
extern "C" void kernel_launch(void* const* d_in, const int* in_sizes, int n_in,
                              void* d_out, int out_size)
{
    const float* x  = (const float*)d_in[0];
    const float* W1 = (const float*)d_in[1];
    const float* U1 = (const float*)d_in[2];
    const float* W2 = (const float*)d_in[3];
    const float* U2 = (const float*)d_in[4];
    const float* Wo = (const float*)d_in[5];
    float* out = (float*)d_out;

    cudaFuncSetAttribute(k_gemm_mma, cudaFuncAttributeMaxDynamicSharedMemorySize,
                         GEMM_SMEM);

    k_init<<<MSZ / 256, 256>>>(U1, U2, W2);
    k_stage<<<dim3(16, 3),  256>>>(1);
    k_stage<<<dim3(16, 6),  256>>>(2);
    k_stage<<<dim3(16, 12), 256>>>(4);
    k_stage<<<dim3(16, 8),  256>>>(8);
    k_tmp<<<dim3(16, 16), 256>>>(W1);
    k_afinal<<<dim3(16, 16), 256>>>(Wo);
    k_gemm_mma<<<dim3(BB / BM, NN / BN), 256, GEMM_SMEM>>>(x, out);
}